// round 4
// baseline (speedup 1.0000x reference)
#include <cuda_runtime.h>

// Problem shape (fixed by reference setup_inputs)
#define BATCH 8
#define MPRED 100
#define NGT   32
#define HWPIX 65536   // 256*256
#define F4_PER_BN (HWPIX / 4)      // 16384 float4 per (b,n) mask
#define GATHER_XBLK 4              // CTAs along the pixel dim per (b,n)
#define F4_PER_BLK (F4_PER_BN / GATHER_XBLK)   // 4096
#define F4_PER_THR (F4_PER_BLK / 256)          // 16

// ---------------------------------------------------------------------------
// Single fused kernel. grid = (4, B*N) = 1024 CTAs, 256 threads.
// Prologue: every CTA redundantly computes the greedy match for its batch
// (cheap: ~1.5K cycles out of shared) -> no second launch, no serialization.
// Main: gather/zero-fill this CTA's quarter of the (b,n) mask with streaming
// cache hints (single-touch data; keep it out of L2's way).
// ---------------------------------------------------------------------------
__global__ void __launch_bounds__(256) fused_kernel(
                             const float* __restrict__ pred_boxes,  // [B,M,4]
                             const float* __restrict__ gt_boxes,    // [B,N,4]
                             const float* __restrict__ pred_scores, // [B,M]
                             const float* __restrict__ pred_masks,  // [B,M,H,W]
                             const float* __restrict__ mask_score,  // [B,M]
                             float* __restrict__ out)
{
    const int bn   = blockIdx.y;    // 0..255
    const int b    = bn >> 5;
    const int n    = bn & 31;
    const int tid  = threadIdx.x;
    const int wid  = tid >> 5;
    const int lane = tid & 31;      // lane = GT index in match phase

    __shared__ float4 s_pbox[MPRED];
    __shared__ float  s_score[MPRED];
    __shared__ float  s_iou[MPRED * NGT];
    __shared__ int    s_hit[128];
    __shared__ int    s_hits[MPRED];
    __shared__ int    s_sorted[MPRED];
    __shared__ int    s_nhits;
    __shared__ int    s_gtm[NGT];
    __shared__ float  s_biou[NGT];

    // ---- Stage boxes + scores (front-batched global loads) ----
    const float4* pb4 = reinterpret_cast<const float4*>(pred_boxes + b * MPRED * 4);
    const float*  ps  = pred_scores + b * MPRED;
    if (tid < MPRED) {
        s_pbox[tid]  = pb4[tid];
        s_score[tid] = ps[tid];
    }
    if (tid < 128) s_hit[tid] = 0;
    __syncthreads();

    // ---- Phase A: IoU matrix + per-pred hit flags (8 warps in parallel) ----
    const float* gb = gt_boxes + (b * NGT + lane) * 4;
    const float g0 = gb[0], g1 = gb[1], g2 = gb[2], g3 = gb[3];
    const float area2 = (g2 - g0) * (g3 - g1);

    for (int p = wid; p < MPRED; p += 8) {
        const float4 pbx = s_pbox[p];       // broadcast LDS
        const float area1 = (pbx.z - pbx.x) * (pbx.w - pbx.y);
        const float lx = fmaxf(pbx.x, g0), ly = fmaxf(pbx.y, g1);
        const float rx = fminf(pbx.z, g2), ry = fminf(pbx.w, g3);
        const float w  = fmaxf(rx - lx, 0.0f);
        const float h  = fmaxf(ry - ly, 0.0f);
        const float inter = w * h;
        const float iou = inter / (area1 + area2 - inter);
        s_iou[p * NGT + lane] = iou;
        const unsigned bal = __ballot_sync(0xffffffffu, iou >= 0.5f);
        if (lane == 0) s_hit[p] = (bal != 0u) && (s_score[p] >= 0.0f);
    }
    __syncthreads();

    // ---- Phase B/C: compaction + stable sort + serial greedy (warp 0) ----
    if (wid == 0) {
        int nh = 0;
        #pragma unroll
        for (int k = 0; k < 4; k++) {
            const int p = k * 32 + lane;
            const int f = (p < MPRED) ? s_hit[p] : 0;
            const unsigned bal = __ballot_sync(0xffffffffu, f != 0);
            if (f) s_hits[nh + __popc(bal & ((1u << lane) - 1u))] = p;
            nh += __popc(bal);
        }
        if (lane == 0) s_nhits = nh;
        __syncwarp();
        const int K = s_nhits;

        // stable descending rank-sort of hit preds (== jnp.argsort(-scores))
        for (int t = lane; t < K; t += 32) {
            const int   hi = s_hits[t];
            const float si = s_score[hi];
            int rank = 0;
            for (int u = 0; u < K; u++) {
                const int   hu = s_hits[u];
                const float su = s_score[hu];
                rank += (su > si) || (su == si && hu < hi);
            }
            s_sorted[rank] = hi;
        }
        __syncwarp();

        int   gtm  = -1;
        float biou = 0.0f;
        for (int t = 0; t < K; t++) {
            const int   i   = s_sorted[t];
            const float iou = s_iou[i * NGT + lane];
            // Faithful to reference: gt available iff gtm <= 0 (intentional "bug")
            const bool  valid = (gtm <= 0) && (iou >= 0.5f);
            const unsigned key  = valid ? __float_as_uint(iou) : 0u;
            const unsigned kmax = __reduce_max_sync(0xffffffffu, key);
            if (kmax != 0u) {
                const unsigned bal = __ballot_sync(0xffffffffu, key == kmax);
                const int m = __ffs(bal) - 1;   // lowest lane = jnp.argmax tie-break
                if (lane == m) { gtm = i; biou = iou; }
            }
        }
        s_gtm[lane]  = gtm;
        s_biou[lane] = biou;
    }
    __syncthreads();

    const int g = s_gtm[n];

    // ---- Tail scalar outputs: one CTA per (b,n) writes its entry ----
    if (blockIdx.x == 0 && tid == 0) {
        float* flags_out = out + (long long)BATCH * NGT * HWPIX;
        float* gtm_out   = flags_out + BATCH * NGT;
        float* biou_out  = gtm_out   + BATCH * NGT;
        flags_out[bn] = (g > -1) ? mask_score[b * MPRED + g] : 0.0f;
        gtm_out[bn]   = (float)g;
        biou_out[bn]  = s_biou[n];
    }

    // ---- Gather / zero-fill this CTA's quarter of the mask ----
    const int base = blockIdx.x * F4_PER_BLK + tid;  // float4 units
    float4* o = reinterpret_cast<float4*>(out) + (long long)bn * F4_PER_BN + base;

    if (g > -1) {
        const float4* src = reinterpret_cast<const float4*>(pred_masks)
                          + (long long)(b * MPRED + g) * F4_PER_BN + base;
        float4 v[F4_PER_THR];
        #pragma unroll
        for (int k = 0; k < F4_PER_THR; k++) v[k] = __ldcs(&src[k * 256]);
        #pragma unroll
        for (int k = 0; k < F4_PER_THR; k++) __stcs(&o[k * 256], v[k]);
    } else {
        const float4 z = make_float4(0.0f, 0.0f, 0.0f, 0.0f);
        #pragma unroll
        for (int k = 0; k < F4_PER_THR; k++) __stcs(&o[k * 256], z);
    }
}

// ---------------------------------------------------------------------------
extern "C" void kernel_launch(void* const* d_in, const int* in_sizes, int n_in,
                              void* d_out, int out_size)
{
    const float* pred_boxes  = (const float*)d_in[0];
    const float* gt_boxes    = (const float*)d_in[1];
    const float* pred_scores = (const float*)d_in[2];
    const float* pred_masks  = (const float*)d_in[3];
    const float* mask_score  = (const float*)d_in[4];
    float* out = (float*)d_out;

    dim3 grid(GATHER_XBLK, BATCH * NGT);   // (4, 256) = 1024 CTAs
    fused_kernel<<<grid, 256>>>(pred_boxes, gt_boxes, pred_scores,
                                pred_masks, mask_score, out);
}

// round 5
// speedup vs baseline: 1.1618x; 1.1618x over previous
#include <cuda_runtime.h>
#include <cstdint>

// Problem shape (fixed by reference setup_inputs)
#define BATCH 8
#define MPRED 100
#define NGT   32
#define HWPIX 65536                     // floats per (b,n) mask
#define BN_BYTES (HWPIX * 4)            // 256 KB per (b,n)
#define GATHER_XBLK 2                   // CTAs along the pixel dim per (b,n)
#define CTA_BYTES (BN_BYTES / GATHER_XBLK)   // 128 KB per CTA
#define CHUNK_BYTES 16384               // TMA chunk
#define NCHUNK (CTA_BYTES / CHUNK_BYTES)     // 8

// Scratch: matched pred index per (b, n).
__device__ int g_gtm[BATCH * NGT];

// ---------------------------------------------------------------------------
// TMA / mbarrier helpers (1D bulk copies, no tensormap needed)
// ---------------------------------------------------------------------------
__device__ __forceinline__ uint32_t smem_u32(const void* p) {
    return (uint32_t)__cvta_generic_to_shared(p);
}
__device__ __forceinline__ void mbar_init(uint32_t mbar, uint32_t cnt) {
    asm volatile("mbarrier.init.shared::cta.b64 [%0], %1;" :: "r"(mbar), "r"(cnt) : "memory");
}
__device__ __forceinline__ void mbar_expect_tx(uint32_t mbar, uint32_t bytes) {
    asm volatile("mbarrier.arrive.expect_tx.shared::cta.b64 _, [%0], %1;"
                 :: "r"(mbar), "r"(bytes) : "memory");
}
__device__ __forceinline__ void mbar_wait(uint32_t mbar, uint32_t parity) {
    uint32_t done;
    do {
        asm volatile("{\n\t.reg .pred p;\n\t"
                     "mbarrier.try_wait.parity.shared::cta.b64 p, [%1], %2;\n\t"
                     "selp.b32 %0, 1, 0, p;\n\t}"
                     : "=r"(done) : "r"(mbar), "r"(parity) : "memory");
    } while (!done);
}
__device__ __forceinline__ void tma_load_1d(uint32_t dst_smem, const void* src,
                                            uint32_t bytes, uint32_t mbar) {
    asm volatile("cp.async.bulk.shared::cta.global.mbarrier::complete_tx::bytes "
                 "[%0], [%1], %2, [%3];"
                 :: "r"(dst_smem), "l"(src), "r"(bytes), "r"(mbar) : "memory");
}
__device__ __forceinline__ void tma_store_1d(void* dst, uint32_t src_smem, uint32_t bytes) {
    asm volatile("cp.async.bulk.global.shared::cta.bulk_group [%0], [%1], %2;"
                 :: "l"(dst), "r"(src_smem), "r"(bytes) : "memory");
}
__device__ __forceinline__ void tma_commit() {
    asm volatile("cp.async.bulk.commit_group;" ::: "memory");
}
template <int N>
__device__ __forceinline__ void tma_wait_group() {
    asm volatile("cp.async.bulk.wait_group %0;" :: "n"(N) : "memory");
}
__device__ __forceinline__ void fence_async_shared() {
    asm volatile("fence.proxy.async.shared::cta;" ::: "memory");
}

// ---------------------------------------------------------------------------
// Kernel 1: per-batch greedy matching (R3 structure, boxes staged in smem).
// One 256-thread block per batch.
// ---------------------------------------------------------------------------
__global__ void match_kernel(const float* __restrict__ pred_boxes,  // [B,M,4]
                             const float* __restrict__ gt_boxes,    // [B,N,4]
                             const float* __restrict__ pred_scores, // [B,M]
                             const float* __restrict__ mask_score,  // [B,M]
                             float* __restrict__ out)
{
    const int b    = blockIdx.x;
    const int tid  = threadIdx.x;
    const int wid  = tid >> 5;
    const int lane = tid & 31;      // lane = GT index

    __shared__ float4 s_pbox[MPRED];
    __shared__ float  s_score[MPRED];
    __shared__ float  s_iou[MPRED * NGT];
    __shared__ int    s_hit[128];
    __shared__ int    s_hits[MPRED];
    __shared__ int    s_sorted[MPRED];
    __shared__ int    s_nhits;

    const float4* pb4 = reinterpret_cast<const float4*>(pred_boxes + b * MPRED * 4);
    const float*  ps  = pred_scores + b * MPRED;
    if (tid < MPRED) { s_pbox[tid] = pb4[tid]; s_score[tid] = ps[tid]; }
    if (tid < 128) s_hit[tid] = 0;
    __syncthreads();

    const float* gb = gt_boxes + (b * NGT + lane) * 4;
    const float g0 = gb[0], g1 = gb[1], g2 = gb[2], g3 = gb[3];
    const float area2 = (g2 - g0) * (g3 - g1);

    // Phase A: each warp handles preds p = wid, wid+8, ...
    for (int p = wid; p < MPRED; p += 8) {
        const float4 pbx = s_pbox[p];
        const float area1 = (pbx.z - pbx.x) * (pbx.w - pbx.y);
        const float lx = fmaxf(pbx.x, g0), ly = fmaxf(pbx.y, g1);
        const float rx = fminf(pbx.z, g2), ry = fminf(pbx.w, g3);
        const float w  = fmaxf(rx - lx, 0.0f);
        const float h  = fmaxf(ry - ly, 0.0f);
        const float inter = w * h;
        const float iou = inter / (area1 + area2 - inter);
        s_iou[p * NGT + lane] = iou;
        const unsigned bal = __ballot_sync(0xffffffffu, iou >= 0.5f);
        if (lane == 0) s_hit[p] = (bal != 0u) && (s_score[p] >= 0.0f);
    }
    __syncthreads();

    if (wid == 0) {
        // compaction
        int nh = 0;
        #pragma unroll
        for (int k = 0; k < 4; k++) {
            const int p = k * 32 + lane;
            const int f = (p < MPRED) ? s_hit[p] : 0;
            const unsigned bal = __ballot_sync(0xffffffffu, f != 0);
            if (f) s_hits[nh + __popc(bal & ((1u << lane) - 1u))] = p;
            nh += __popc(bal);
        }
        if (lane == 0) s_nhits = nh;
        __syncwarp();
        const int K = s_nhits;

        // stable descending rank-sort (== jnp.argsort(-scores) on hit set)
        for (int t = lane; t < K; t += 32) {
            const int   hi = s_hits[t];
            const float si = s_score[hi];
            int rank = 0;
            for (int u = 0; u < K; u++) {
                const int   hu = s_hits[u];
                const float su = s_score[hu];
                rank += (su > si) || (su == si && hu < hi);
            }
            s_sorted[rank] = hi;
        }
        __syncwarp();

        // serial greedy scan
        int   gtm  = -1;
        float biou = 0.0f;
        for (int t = 0; t < K; t++) {
            const int   i   = s_sorted[t];
            const float iou = s_iou[i * NGT + lane];
            // Faithful to reference: gt available iff gtm <= 0 (intentional "bug")
            const bool  valid = (gtm <= 0) && (iou >= 0.5f);
            const unsigned key  = valid ? __float_as_uint(iou) : 0u;
            const unsigned kmax = __reduce_max_sync(0xffffffffu, key);
            if (kmax != 0u) {
                const unsigned bal = __ballot_sync(0xffffffffu, key == kmax);
                const int m = __ffs(bal) - 1;   // lowest lane = jnp.argmax tie-break
                if (lane == m) { gtm = i; biou = iou; }
            }
        }

        const int bn = b * NGT + lane;
        g_gtm[bn] = gtm;

        float* flags_out = out + (long long)BATCH * NGT * HWPIX;
        float* gtm_out   = flags_out + BATCH * NGT;
        float* biou_out  = gtm_out   + BATCH * NGT;
        flags_out[bn] = (gtm > -1) ? mask_score[b * MPRED + gtm] : 0.0f;
        gtm_out[bn]   = (float)gtm;
        biou_out[bn]  = biou;
    }
}

// ---------------------------------------------------------------------------
// Kernel 2: TMA bulk gather / zero-fill.
// grid (2, 256) = 512 CTAs, 128 threads. Each CTA owns 128 KB = 8 x 16 KB.
// Matched: double-buffered TMA load->store through smem.
// Unmatched: TMA-store a zeroed smem tile 8x.
// ---------------------------------------------------------------------------
__global__ void __launch_bounds__(128) gather_kernel(
                              const float* __restrict__ pred_masks, // [B,M,H,W]
                              float* __restrict__ out)              // [B,N,H,W]
{
    __shared__ alignas(128) char buf[2][CHUNK_BYTES];
    __shared__ uint64_t mbar_mem[2];

    const int bn = blockIdx.y;
    const int b  = bn >> 5;
    const int g  = g_gtm[bn];
    const int tid = threadIdx.x;

    const uint32_t mb0 = smem_u32(&mbar_mem[0]);
    const uint32_t mb1 = smem_u32(&mbar_mem[1]);
    const uint32_t sb0 = smem_u32(&buf[0][0]);
    const uint32_t sb1 = smem_u32(&buf[1][0]);

    char* dst = (char*)out + (long long)bn * BN_BYTES + (long long)blockIdx.x * CTA_BYTES;

    if (g > -1) {
        // ---- matched: pipelined TMA copy ----
        if (tid == 0) { mbar_init(mb0, 1); mbar_init(mb1, 1); }
        __syncthreads();
        if (tid == 0) fence_async_shared();  // order mbarrier init before TMA use

        if (tid == 0) {
            const char* src = (const char*)pred_masks
                            + (long long)(b * MPRED + g) * BN_BYTES
                            + (long long)blockIdx.x * CTA_BYTES;
            #pragma unroll
            for (int c = 0; c < NCHUNK; c++) {
                const uint32_t bi   = c & 1;
                const uint32_t ph   = (c >> 1) & 1;
                const uint32_t smb  = bi ? sb1 : sb0;
                const uint32_t mbb  = bi ? mb1 : mb0;
                if (c >= 2) tma_wait_group<1>();   // store from this buf (c-2) done
                mbar_expect_tx(mbb, CHUNK_BYTES);
                tma_load_1d(smb, src + (long long)c * CHUNK_BYTES, CHUNK_BYTES, mbb);
                mbar_wait(mbb, ph);
                tma_store_1d(dst + (long long)c * CHUNK_BYTES, smb, CHUNK_BYTES);
                tma_commit();
            }
            tma_wait_group<0>();
        }
        __syncthreads();
    } else {
        // ---- unmatched: zero smem tile, TMA-store it 8x ----
        float4* zb = reinterpret_cast<float4*>(&buf[0][0]);
        const float4 z = make_float4(0.0f, 0.0f, 0.0f, 0.0f);
        #pragma unroll
        for (int k = 0; k < CHUNK_BYTES / 16 / 128; k++)   // 8 iters x 128 thr
            zb[k * 128 + tid] = z;
        __syncthreads();
        if (tid == 0) {
            fence_async_shared();   // generic STS -> async-proxy read ordering
            #pragma unroll
            for (int c = 0; c < NCHUNK; c++)
                tma_store_1d(dst + (long long)c * CHUNK_BYTES, sb0, CHUNK_BYTES);
            tma_commit();
            tma_wait_group<0>();
        }
        __syncthreads();
    }
}

// ---------------------------------------------------------------------------
extern "C" void kernel_launch(void* const* d_in, const int* in_sizes, int n_in,
                              void* d_out, int out_size)
{
    const float* pred_boxes  = (const float*)d_in[0];
    const float* gt_boxes    = (const float*)d_in[1];
    const float* pred_scores = (const float*)d_in[2];
    const float* pred_masks  = (const float*)d_in[3];
    const float* mask_score  = (const float*)d_in[4];
    float* out = (float*)d_out;

    match_kernel<<<BATCH, 256>>>(pred_boxes, gt_boxes, pred_scores, mask_score, out);

    dim3 grid(GATHER_XBLK, BATCH * NGT);   // (2, 256) = 512 CTAs, single wave
    gather_kernel<<<grid, 128>>>(pred_masks, out);
}

// round 6
// speedup vs baseline: 1.3017x; 1.1204x over previous
#include <cuda_runtime.h>
#include <cstdint>

// Problem shape (fixed by reference setup_inputs)
#define BATCH 8
#define MPRED 100
#define NGT   32
#define HWPIX 65536   // 256*256
#define F4_PER_BN (HWPIX / 4)                  // 16384 float4 per (b,n)
#define GXBLK 4                                 // gather CTAs per (b,n)
#define F4_PER_BLK (F4_PER_BN / GXBLK)          // 4096
#define F4_PER_THR (F4_PER_BLK / 256)           // 16
#define NMATCH BATCH                            // match CTAs (block 0..7)

// Cross-CTA sync: sentinel word per (b,n) carrying gtm+2 (0 = not ready),
// plus consumer counters for replay-safe reset. Zero-initialized.
__device__ int g_sync[BATCH * NGT];
__device__ int g_cnt[BATCH * NGT];

// ---------------------------------------------------------------------------
// Fused kernel. grid = 8 + B*N*GXBLK = 1032 CTAs, 256 threads.
//   blocks 0..7     : greedy match for batch b (writes sentinels + tail outputs)
//   blocks 8..1031  : spin on sentinel, then gather/zero-fill a mask quarter
// ---------------------------------------------------------------------------
__global__ void __launch_bounds__(256, 7) fused_kernel(
                             const float* __restrict__ pred_boxes,  // [B,M,4]
                             const float* __restrict__ gt_boxes,    // [B,N,4]
                             const float* __restrict__ pred_scores, // [B,M]
                             const float* __restrict__ pred_masks,  // [B,M,H,W]
                             const float* __restrict__ mask_score,  // [B,M]
                             float* __restrict__ out)
{
    const int tid  = threadIdx.x;

    if (blockIdx.x < NMATCH) {
        // =================== MATCH PATH ===================
        const int b    = blockIdx.x;
        const int wid  = tid >> 5;
        const int lane = tid & 31;      // lane = GT index

        __shared__ float4 s_pbox[MPRED];
        __shared__ float  s_score[MPRED];
        __shared__ float  s_iou[MPRED * NGT];
        __shared__ int    s_hit[128];
        __shared__ int    s_hits[MPRED];
        __shared__ int    s_sorted[MPRED];
        __shared__ int    s_nhits;

        const float4* pb4 = reinterpret_cast<const float4*>(pred_boxes + b * MPRED * 4);
        const float*  ps  = pred_scores + b * MPRED;
        if (tid < MPRED) { s_pbox[tid] = pb4[tid]; s_score[tid] = ps[tid]; }
        if (tid < 128) s_hit[tid] = 0;
        __syncthreads();

        const float* gb = gt_boxes + (b * NGT + lane) * 4;
        const float g0 = gb[0], g1 = gb[1], g2 = gb[2], g3 = gb[3];
        const float area2 = (g2 - g0) * (g3 - g1);

        // Phase A: IoU matrix + per-pred hit flags (8 warps in parallel)
        for (int p = wid; p < MPRED; p += 8) {
            const float4 pbx = s_pbox[p];
            const float area1 = (pbx.z - pbx.x) * (pbx.w - pbx.y);
            const float lx = fmaxf(pbx.x, g0), ly = fmaxf(pbx.y, g1);
            const float rx = fminf(pbx.z, g2), ry = fminf(pbx.w, g3);
            const float w  = fmaxf(rx - lx, 0.0f);
            const float h  = fmaxf(ry - ly, 0.0f);
            const float inter = w * h;
            const float iou = inter / (area1 + area2 - inter);
            s_iou[p * NGT + lane] = iou;
            const unsigned bal = __ballot_sync(0xffffffffu, iou >= 0.5f);
            if (lane == 0) s_hit[p] = (bal != 0u) && (s_score[p] >= 0.0f);
        }
        __syncthreads();

        if (wid == 0) {
            // compaction via ballots + prefix popcount
            int nh = 0;
            #pragma unroll
            for (int k = 0; k < 4; k++) {
                const int p = k * 32 + lane;
                const int f = (p < MPRED) ? s_hit[p] : 0;
                const unsigned bal = __ballot_sync(0xffffffffu, f != 0);
                if (f) s_hits[nh + __popc(bal & ((1u << lane) - 1u))] = p;
                nh += __popc(bal);
            }
            if (lane == 0) s_nhits = nh;
            __syncwarp();
            const int K = s_nhits;

            // stable descending rank-sort (== jnp.argsort(-scores) on hit set)
            for (int t = lane; t < K; t += 32) {
                const int   hi = s_hits[t];
                const float si = s_score[hi];
                int rank = 0;
                for (int u = 0; u < K; u++) {
                    const int   hu = s_hits[u];
                    const float su = s_score[hu];
                    rank += (su > si) || (su == si && hu < hi);
                }
                s_sorted[rank] = hi;
            }
            __syncwarp();

            // serial greedy scan
            int   gtm  = -1;
            float biou = 0.0f;
            for (int t = 0; t < K; t++) {
                const int   i   = s_sorted[t];
                const float iou = s_iou[i * NGT + lane];
                // Faithful to reference: gt available iff gtm <= 0 (intentional "bug")
                const bool  valid = (gtm <= 0) && (iou >= 0.5f);
                const unsigned key  = valid ? __float_as_uint(iou) : 0u;
                const unsigned kmax = __reduce_max_sync(0xffffffffu, key);
                if (kmax != 0u) {
                    const unsigned bal = __ballot_sync(0xffffffffu, key == kmax);
                    const int m = __ffs(bal) - 1;   // lowest lane = jnp.argmax
                    if (lane == m) { gtm = i; biou = iou; }
                }
            }

            // Tail scalar outputs
            const int bn = b * NGT + lane;
            float* flags_out = out + (long long)BATCH * NGT * HWPIX;
            float* gtm_out   = flags_out + BATCH * NGT;
            float* biou_out  = gtm_out   + BATCH * NGT;
            flags_out[bn] = (gtm > -1) ? mask_score[b * MPRED + gtm] : 0.0f;
            gtm_out[bn]   = (float)gtm;
            biou_out[bn]  = biou;

            // Release: sentinel carries the payload (gtm+2, always nonzero)
            atomicExch(&g_sync[bn], gtm + 2);
        }
    } else {
        // =================== GATHER PATH ===================
        const int u  = blockIdx.x - NMATCH;   // 0..1023
        const int bn = u >> 2;                // (b,n) id
        const int b  = bn >> 5;
        const int xq = u & 3;                 // quarter index

        // Spin until the match CTA for this batch publishes gtm for bn.
        volatile int* sy = (volatile int*)&g_sync[bn];
        int v = *sy;
        while (v == 0) { __nanosleep(64); v = *sy; }
        const int g = v - 2;

        const int base = xq * F4_PER_BLK + tid;   // float4 units
        float4* o = reinterpret_cast<float4*>(out) + (long long)bn * F4_PER_BN + base;

        if (g > -1) {
            const float4* src = reinterpret_cast<const float4*>(pred_masks)
                              + (long long)(b * MPRED + g) * F4_PER_BN + base;
            #pragma unroll
            for (int k = 0; k < F4_PER_THR; k++) o[k * 256] = src[k * 256];
        } else {
            const float4 z = make_float4(0.0f, 0.0f, 0.0f, 0.0f);
            #pragma unroll
            for (int k = 0; k < F4_PER_THR; k++) o[k * 256] = z;
        }

        // Replay-safe reset: 4th consumer CTA clears sentinel + counter.
        __syncthreads();
        if (tid == 0) {
            const int old = atomicAdd(&g_cnt[bn], 1);
            if (old == 3) {
                *(volatile int*)&g_cnt[bn]  = 0;
                *(volatile int*)&g_sync[bn] = 0;
            }
        }
    }
}

// ---------------------------------------------------------------------------
extern "C" void kernel_launch(void* const* d_in, const int* in_sizes, int n_in,
                              void* d_out, int out_size)
{
    const float* pred_boxes  = (const float*)d_in[0];
    const float* gt_boxes    = (const float*)d_in[1];
    const float* pred_scores = (const float*)d_in[2];
    const float* pred_masks  = (const float*)d_in[3];
    const float* mask_score  = (const float*)d_in[4];
    float* out = (float*)d_out;

    const int nblk = NMATCH + BATCH * NGT * GXBLK;   // 8 + 1024 = 1032
    fused_kernel<<<nblk, 256>>>(pred_boxes, gt_boxes, pred_scores,
                                pred_masks, mask_score, out);
}

// round 7
// speedup vs baseline: 1.5656x; 1.2027x over previous
#include <cuda_runtime.h>
#include <cstdint>

// Problem shape (fixed by reference setup_inputs)
#define BATCH 8
#define MPRED 100
#define NGT   32
#define HWPIX 65536   // 256*256
#define F4_PER_BN (HWPIX / 4)                  // 16384 float4 per (b,n)
#define GXBLK 4                                 // gather CTAs per (b,n)
#define F4_PER_BLK (F4_PER_BN / GXBLK)          // 4096
#define F4_PER_THR (F4_PER_BLK / 256)           // 16 float4 per thread
#define NCHUNK 4                                // speculation chunks per CTA
#define IT_PER_CHUNK (F4_PER_THR / NCHUNK)      // 4 iters (16 KB per CTA-chunk)
#define NMATCH BATCH                            // match CTAs (block 0..7)

// Cross-CTA sync: sentinel word per (b,n) carrying gtm+2 (0 = not ready),
// plus consumer counters for replay-safe reset. Zero-initialized.
__device__ int g_sync[BATCH * NGT];
__device__ int g_cnt[BATCH * NGT];

// ---------------------------------------------------------------------------
// Fused kernel. grid = 8 + B*N*GXBLK = 1032 CTAs, 256 threads.
//   blocks 0..7    : greedy match for batch b (publishes sentinels early)
//   blocks 8..1031 : adaptive-speculative gather: zero-fill chunks while the
//                    match is unknown (74% useful), poll once per chunk, then
//                    copy (and redo speculated chunks) if matched.
// ---------------------------------------------------------------------------
__global__ void __launch_bounds__(256, 7) fused_kernel(
                             const float* __restrict__ pred_boxes,  // [B,M,4]
                             const float* __restrict__ gt_boxes,    // [B,N,4]
                             const float* __restrict__ pred_scores, // [B,M]
                             const float* __restrict__ pred_masks,  // [B,M,H,W]
                             const float* __restrict__ mask_score,  // [B,M]
                             float* __restrict__ out)
{
    const int tid = threadIdx.x;

    if (blockIdx.x < NMATCH) {
        // =================== MATCH PATH ===================
        const int b    = blockIdx.x;
        const int wid  = tid >> 5;
        const int lane = tid & 31;      // lane = GT index

        __shared__ float4 s_pbox[MPRED];
        __shared__ float  s_score[MPRED];
        __shared__ float  s_iou[MPRED * NGT];
        __shared__ int    s_hit[128];
        __shared__ int    s_hits[MPRED];
        __shared__ int    s_sorted[MPRED];
        __shared__ int    s_nhits;

        const float4* pb4 = reinterpret_cast<const float4*>(pred_boxes + b * MPRED * 4);
        const float*  ps  = pred_scores + b * MPRED;
        if (tid < MPRED) { s_pbox[tid] = pb4[tid]; s_score[tid] = ps[tid]; }
        if (tid < 128) s_hit[tid] = 0;
        __syncthreads();

        const float* gb = gt_boxes + (b * NGT + lane) * 4;
        const float g0 = gb[0], g1 = gb[1], g2 = gb[2], g3 = gb[3];
        const float area2 = (g2 - g0) * (g3 - g1);

        // Phase A: IoU matrix + per-pred hit flags (8 warps in parallel)
        for (int p = wid; p < MPRED; p += 8) {
            const float4 pbx = s_pbox[p];
            const float area1 = (pbx.z - pbx.x) * (pbx.w - pbx.y);
            const float lx = fmaxf(pbx.x, g0), ly = fmaxf(pbx.y, g1);
            const float rx = fminf(pbx.z, g2), ry = fminf(pbx.w, g3);
            const float w  = fmaxf(rx - lx, 0.0f);
            const float h  = fmaxf(ry - ly, 0.0f);
            const float inter = w * h;
            const float iou = inter / (area1 + area2 - inter);
            s_iou[p * NGT + lane] = iou;
            const unsigned bal = __ballot_sync(0xffffffffu, iou >= 0.5f);
            if (lane == 0) s_hit[p] = (bal != 0u) && (s_score[p] >= 0.0f);
        }
        __syncthreads();

        if (wid == 0) {
            // compaction via ballots + prefix popcount
            int nh = 0;
            #pragma unroll
            for (int k = 0; k < 4; k++) {
                const int p = k * 32 + lane;
                const int f = (p < MPRED) ? s_hit[p] : 0;
                const unsigned bal = __ballot_sync(0xffffffffu, f != 0);
                if (f) s_hits[nh + __popc(bal & ((1u << lane) - 1u))] = p;
                nh += __popc(bal);
            }
            if (lane == 0) s_nhits = nh;
            __syncwarp();
            const int K = s_nhits;

            // stable descending rank-sort (== jnp.argsort(-scores) on hit set)
            for (int t = lane; t < K; t += 32) {
                const int   hi = s_hits[t];
                const float si = s_score[hi];
                int rank = 0;
                for (int u = 0; u < K; u++) {
                    const int   hu = s_hits[u];
                    const float su = s_score[hu];
                    rank += (su > si) || (su == si && hu < hi);
                }
                s_sorted[rank] = hi;
            }
            __syncwarp();

            // serial greedy scan
            int   gtm  = -1;
            float biou = 0.0f;
            for (int t = 0; t < K; t++) {
                const int   i   = s_sorted[t];
                const float iou = s_iou[i * NGT + lane];
                // Faithful to reference: gt available iff gtm <= 0 (intentional "bug")
                const bool  valid = (gtm <= 0) && (iou >= 0.5f);
                const unsigned key  = valid ? __float_as_uint(iou) : 0u;
                const unsigned kmax = __reduce_max_sync(0xffffffffu, key);
                if (kmax != 0u) {
                    const unsigned bal = __ballot_sync(0xffffffffu, key == kmax);
                    const int m = __ffs(bal) - 1;   // lowest lane = jnp.argmax
                    if (lane == m) { gtm = i; biou = iou; }
                }
            }

            // Publish FIRST (payload in flag, single word, nonzero)
            const int bn = b * NGT + lane;
            atomicExch(&g_sync[bn], gtm + 2);

            // Tail scalar outputs (off the critical path)
            float* flags_out = out + (long long)BATCH * NGT * HWPIX;
            float* gtm_out   = flags_out + BATCH * NGT;
            float* biou_out  = gtm_out   + BATCH * NGT;
            flags_out[bn] = (gtm > -1) ? mask_score[b * MPRED + gtm] : 0.0f;
            gtm_out[bn]   = (float)gtm;
            biou_out[bn]  = biou;
        }
    } else {
        // =================== GATHER PATH ===================
        const int u  = blockIdx.x - NMATCH;   // 0..1023
        const int bn = u >> 2;
        const int b  = bn >> 5;
        const int xq = u & 3;                 // quarter index

        __shared__ int sh_g;                  // -2 = unknown, else gtm

        volatile int* sy = (volatile int*)&g_sync[bn];

        if (tid == 0) { const int v = *sy; sh_g = v ? (v - 2) : -2; }
        __syncthreads();
        int g = sh_g;

        const int base = xq * F4_PER_BLK + tid;   // float4 units
        float4* o = reinterpret_cast<float4*>(out) + (long long)bn * F4_PER_BN + base;
        const float4 z = make_float4(0.0f, 0.0f, 0.0f, 0.0f);

        int zeroed = 0;   // chunks written speculatively as zero

        #pragma unroll
        for (int c = 0; c < NCHUNK; c++) {
            if (g >= 0) {
                // known matched: copy this chunk
                const float4* src = reinterpret_cast<const float4*>(pred_masks)
                                  + (long long)(b * MPRED + g) * F4_PER_BN + base;
                #pragma unroll
                for (int k = 0; k < IT_PER_CHUNK; k++)
                    o[(c * IT_PER_CHUNK + k) * 256] = src[(c * IT_PER_CHUNK + k) * 256];
            } else {
                // unknown or unmatched: write zeros (74% chance this is final)
                #pragma unroll
                for (int k = 0; k < IT_PER_CHUNK; k++)
                    o[(c * IT_PER_CHUNK + k) * 256] = z;
                if (g == -2) {
                    zeroed = c + 1;
                    // poll once per chunk (thread 0 only), uniform broadcast
                    __syncthreads();
                    if (tid == 0) { const int v = *sy; sh_g = v ? (v - 2) : -2; }
                    __syncthreads();
                    g = sh_g;
                }
            }
        }

        // Still unknown after zeroing everything: spin (thread 0 only)
        if (g == -2) {
            if (tid == 0) {
                int v = *sy;
                while (v == 0) { __nanosleep(128); v = *sy; }
                sh_g = v - 2;
            }
            __syncthreads();
            g = sh_g;
        }

        // Matched: redo the speculatively-zeroed chunks with real data.
        // (Same threads, same addresses -> program order guarantees final value.)
        if (g > -1) {
            const float4* src = reinterpret_cast<const float4*>(pred_masks)
                              + (long long)(b * MPRED + g) * F4_PER_BN + base;
            for (int c = 0; c < zeroed; c++) {
                #pragma unroll
                for (int k = 0; k < IT_PER_CHUNK; k++)
                    o[(c * IT_PER_CHUNK + k) * 256] = src[(c * IT_PER_CHUNK + k) * 256];
            }
        }

        // Replay-safe reset: 4th consumer CTA clears sentinel + counter.
        __syncthreads();
        if (tid == 0) {
            const int old = atomicAdd(&g_cnt[bn], 1);
            if (old == 3) {
                *(volatile int*)&g_cnt[bn]  = 0;
                *(volatile int*)&g_sync[bn] = 0;
            }
        }
    }
}

// ---------------------------------------------------------------------------
extern "C" void kernel_launch(void* const* d_in, const int* in_sizes, int n_in,
                              void* d_out, int out_size)
{
    const float* pred_boxes  = (const float*)d_in[0];
    const float* gt_boxes    = (const float*)d_in[1];
    const float* pred_scores = (const float*)d_in[2];
    const float* pred_masks  = (const float*)d_in[3];
    const float* mask_score  = (const float*)d_in[4];
    float* out = (float*)d_out;

    const int nblk = NMATCH + BATCH * NGT * GXBLK;   // 8 + 1024 = 1032
    fused_kernel<<<nblk, 256>>>(pred_boxes, gt_boxes, pred_scores,
                                pred_masks, mask_score, out);
}

// round 8
// speedup vs baseline: 1.5872x; 1.0138x over previous
#include <cuda_runtime.h>
#include <cstdint>

// Problem shape (fixed by reference setup_inputs)
#define BATCH 8
#define MPRED 100
#define NGT   32
#define HWPIX 65536   // 256*256
#define F4_PER_BN (HWPIX / 4)                  // 16384 float4 per (b,n)
#define GXBLK 4                                 // gather CTAs per (b,n)
#define F4_PER_BLK (F4_PER_BN / GXBLK)          // 4096
#define F4_PER_THR (F4_PER_BLK / 256)           // 16 float4 per thread
#define NCHUNK 8                                // speculation chunks per CTA
#define IT_PER_CHUNK (F4_PER_THR / NCHUNK)      // 2 iters (8 KB per CTA-chunk)
#define NMATCH BATCH                            // match CTAs (block 0..7)

// Cross-CTA sync: sentinel word per (b,n) carrying gtm+2 (0 = not ready),
// plus consumer counters for replay-safe reset. Zero-initialized.
__device__ int g_sync[BATCH * NGT];
__device__ int g_cnt[BATCH * NGT];

// ---------------------------------------------------------------------------
// Fused kernel. grid = 8 + B*N*GXBLK = 1032 CTAs, 256 threads.
//   blocks 0..7    : greedy match for batch b (publishes sentinels early)
//   blocks 8..1031 : adaptive-speculative gather with latency-hidden polling.
// ---------------------------------------------------------------------------
__global__ void __launch_bounds__(256, 7) fused_kernel(
                             const float* __restrict__ pred_boxes,  // [B,M,4]
                             const float* __restrict__ gt_boxes,    // [B,N,4]
                             const float* __restrict__ pred_scores, // [B,M]
                             const float* __restrict__ pred_masks,  // [B,M,H,W]
                             const float* __restrict__ mask_score,  // [B,M]
                             float* __restrict__ out)
{
    const int tid = threadIdx.x;

    if (blockIdx.x < NMATCH) {
        // =================== MATCH PATH ===================
        const int b    = blockIdx.x;
        const int wid  = tid >> 5;
        const int lane = tid & 31;      // lane = GT index

        __shared__ float4 s_pbox[MPRED];
        __shared__ float  s_score[MPRED];
        __shared__ float  s_iou[MPRED * NGT];
        __shared__ int    s_hit[128];
        __shared__ int    s_hits[MPRED];
        __shared__ int    s_sorted[MPRED];
        __shared__ int    s_nhits;

        const float4* pb4 = reinterpret_cast<const float4*>(pred_boxes + b * MPRED * 4);
        const float*  ps  = pred_scores + b * MPRED;
        if (tid < MPRED) { s_pbox[tid] = pb4[tid]; s_score[tid] = ps[tid]; }
        if (tid < 128) s_hit[tid] = 0;
        __syncthreads();

        const float* gb = gt_boxes + (b * NGT + lane) * 4;
        const float g0 = gb[0], g1 = gb[1], g2 = gb[2], g3 = gb[3];
        const float area2 = (g2 - g0) * (g3 - g1);

        // Phase A: IoU matrix + per-pred hit flags (8 warps in parallel).
        // __fdividef: MUFU.RCP-based; ~2^-22 rel err, fine at 1e-3 tolerance.
        for (int p = wid; p < MPRED; p += 8) {
            const float4 pbx = s_pbox[p];
            const float area1 = (pbx.z - pbx.x) * (pbx.w - pbx.y);
            const float lx = fmaxf(pbx.x, g0), ly = fmaxf(pbx.y, g1);
            const float rx = fminf(pbx.z, g2), ry = fminf(pbx.w, g3);
            const float w  = fmaxf(rx - lx, 0.0f);
            const float h  = fmaxf(ry - ly, 0.0f);
            const float inter = w * h;
            const float iou = __fdividef(inter, area1 + area2 - inter);
            s_iou[p * NGT + lane] = iou;
            const unsigned bal = __ballot_sync(0xffffffffu, iou >= 0.5f);
            if (lane == 0) s_hit[p] = (bal != 0u) && (s_score[p] >= 0.0f);
        }
        __syncthreads();

        if (wid == 0) {
            // compaction via ballots + prefix popcount
            int nh = 0;
            #pragma unroll
            for (int k = 0; k < 4; k++) {
                const int p = k * 32 + lane;
                const int f = (p < MPRED) ? s_hit[p] : 0;
                const unsigned bal = __ballot_sync(0xffffffffu, f != 0);
                if (f) s_hits[nh + __popc(bal & ((1u << lane) - 1u))] = p;
                nh += __popc(bal);
            }
            if (lane == 0) s_nhits = nh;
            __syncwarp();
            const int K = s_nhits;

            // stable descending rank-sort (== jnp.argsort(-scores) on hit set)
            for (int t = lane; t < K; t += 32) {
                const int   hi = s_hits[t];
                const float si = s_score[hi];
                int rank = 0;
                for (int u = 0; u < K; u++) {
                    const int   hu = s_hits[u];
                    const float su = s_score[hu];
                    rank += (su > si) || (su == si && hu < hi);
                }
                s_sorted[rank] = hi;
            }
            __syncwarp();

            // serial greedy scan
            int   gtm  = -1;
            float biou = 0.0f;
            for (int t = 0; t < K; t++) {
                const int   i   = s_sorted[t];
                const float iou = s_iou[i * NGT + lane];
                // Faithful to reference: gt available iff gtm <= 0 (intentional "bug")
                const bool  valid = (gtm <= 0) && (iou >= 0.5f);
                const unsigned key  = valid ? __float_as_uint(iou) : 0u;
                const unsigned kmax = __reduce_max_sync(0xffffffffu, key);
                if (kmax != 0u) {
                    const unsigned bal = __ballot_sync(0xffffffffu, key == kmax);
                    const int m = __ffs(bal) - 1;   // lowest lane = jnp.argmax
                    if (lane == m) { gtm = i; biou = iou; }
                }
            }

            // Publish FIRST (payload in flag, single word, nonzero)
            const int bn = b * NGT + lane;
            atomicExch(&g_sync[bn], gtm + 2);

            // Tail scalar outputs (off the critical path)
            float* flags_out = out + (long long)BATCH * NGT * HWPIX;
            float* gtm_out   = flags_out + BATCH * NGT;
            float* biou_out  = gtm_out   + BATCH * NGT;
            flags_out[bn] = (gtm > -1) ? mask_score[b * MPRED + gtm] : 0.0f;
            gtm_out[bn]   = (float)gtm;
            biou_out[bn]  = biou;
        }
    } else {
        // =================== GATHER PATH ===================
        const int u  = blockIdx.x - NMATCH;   // 0..1023
        const int bn = u >> 2;
        const int b  = bn >> 5;
        const int xq = u & 3;                 // quarter index

        __shared__ int sh_g;                  // -2 = unknown, else gtm

        volatile int* sy = (volatile int*)&g_sync[bn];

        if (tid == 0) { const int v = *sy; sh_g = v ? (v - 2) : -2; }
        __syncthreads();
        int g = sh_g;

        const int base = xq * F4_PER_BLK + tid;   // float4 units
        float4* o = reinterpret_cast<float4*>(out) + (long long)bn * F4_PER_BN + base;
        const float4 z = make_float4(0.0f, 0.0f, 0.0f, 0.0f);

        int zeroed = 0;   // chunks written speculatively as zero

        #pragma unroll
        for (int c = 0; c < NCHUNK; c++) {
            if (g >= 0) {
                // known matched: copy this chunk
                const float4* src = reinterpret_cast<const float4*>(pred_masks)
                                  + (long long)(b * MPRED + g) * F4_PER_BN + base;
                #pragma unroll
                for (int k = 0; k < IT_PER_CHUNK; k++)
                    o[(c * IT_PER_CHUNK + k) * 256] = src[(c * IT_PER_CHUNK + k) * 256];
            } else if (g == -2) {
                // unknown: issue the poll load FIRST, hide its latency
                // behind the zero-fill stores, consume after.
                int v = 0;
                if (tid == 0) v = *sy;             // in-flight during stores
                #pragma unroll
                for (int k = 0; k < IT_PER_CHUNK; k++)
                    o[(c * IT_PER_CHUNK + k) * 256] = z;
                zeroed = c + 1;
                if (tid == 0) sh_g = v ? (v - 2) : -2;
                __syncthreads();
                g = sh_g;
            } else {
                // known unmatched: zeros are final
                #pragma unroll
                for (int k = 0; k < IT_PER_CHUNK; k++)
                    o[(c * IT_PER_CHUNK + k) * 256] = z;
            }
        }

        // Still unknown after zeroing everything: spin (thread 0 only)
        if (g == -2) {
            if (tid == 0) {
                int v = *sy;
                while (v == 0) { __nanosleep(128); v = *sy; }
                sh_g = v - 2;
            }
            __syncthreads();
            g = sh_g;
        }

        // Matched: redo the speculatively-zeroed chunks with real data.
        // (Same threads, same addresses -> program order guarantees final value.)
        if (g > -1) {
            const float4* src = reinterpret_cast<const float4*>(pred_masks)
                              + (long long)(b * MPRED + g) * F4_PER_BN + base;
            for (int c = 0; c < zeroed; c++) {
                #pragma unroll
                for (int k = 0; k < IT_PER_CHUNK; k++)
                    o[(c * IT_PER_CHUNK + k) * 256] = src[(c * IT_PER_CHUNK + k) * 256];
            }
        }

        // Replay-safe reset: 4th consumer CTA clears sentinel + counter.
        __syncthreads();
        if (tid == 0) {
            const int old = atomicAdd(&g_cnt[bn], 1);
            if (old == 3) {
                *(volatile int*)&g_cnt[bn]  = 0;
                *(volatile int*)&g_sync[bn] = 0;
            }
        }
    }
}

// ---------------------------------------------------------------------------
extern "C" void kernel_launch(void* const* d_in, const int* in_sizes, int n_in,
                              void* d_out, int out_size)
{
    const float* pred_boxes  = (const float*)d_in[0];
    const float* gt_boxes    = (const float*)d_in[1];
    const float* pred_scores = (const float*)d_in[2];
    const float* pred_masks  = (const float*)d_in[3];
    const float* mask_score  = (const float*)d_in[4];
    float* out = (float*)d_out;

    const int nblk = NMATCH + BATCH * NGT * GXBLK;   // 8 + 1024 = 1032
    fused_kernel<<<nblk, 256>>>(pred_boxes, gt_boxes, pred_scores,
                                pred_masks, mask_score, out);
}